// round 11
// baseline (speedup 1.0000x reference)
#include <cuda_runtime.h>
#include <math.h>

// Shapes
// x:  [32, 112, 112, 128] fp32  -> B=32, HW=12544, C=128
// w1: [128, 2048], b1: [2048], w2: [2048, 128], b2: [128]
#define B      32
#define HW     12544
#define C      128
#define R      2048
#define NSPLIT 98
#define F4_PER_B  (HW * C / 4)               // 401408 float4 per batch
#define F4_PER_BLK (128 * C / 4)             // 4096 float4 per split
#define GBATCH  16                           // batches per group (102.8 MB < L2)
#define NGROUPS (B / GBATCH)                 // 2

// Scratch (device globals: allocation-free; zero-init at load, self-resetting)
__device__ __align__(16) float g_partial[B * NSPLIT * C];  // 1.6 MB pool partials
__device__ __align__(16) float g_gate[B * C];              // final sigmoid gates
__device__ unsigned g_bcnt[B];                             // per-batch arrival counters

// ---------------------------------------------------------------------------
// Kernel 1: pool + fused excite.  grid (NSPLIT, GBATCH), 256 threads.
// Each block sums 128 rows of one batch (channel group fixed per thread since
// 256 % 32 == 0).  The LAST block of each batch (per-batch atomic counter,
// self-resetting -> graph-replay safe) additionally computes the whole excite
// path for that batch: reduce -> GEMM1+tanh-GELU -> split-K GEMM2 -> sigmoid.
// Early batches' excites overlap later batches' pooling.
// ---------------------------------------------------------------------------
__global__ __launch_bounds__(256, 6)
void se_pool_excite_kernel(const float* __restrict__ x,
                           const float* __restrict__ w1, const float* __restrict__ b1,
                           const float* __restrict__ w2, const float* __restrict__ b2,
                           int g) {
    const int b = g * GBATCH + blockIdx.y;
    const int split = blockIdx.x;
    const int t = threadIdx.x;
    const float4* __restrict__ xb =
        reinterpret_cast<const float4*>(x) + (size_t)b * F4_PER_B + (size_t)split * F4_PER_BLK;

    // ---- pooling partial sum for this split ----
    float4 acc4 = make_float4(0.f, 0.f, 0.f, 0.f);
#pragma unroll
    for (int i = 0; i < 16; i++) {           // 16 * 256 = 4096 float4
        float4 v = xb[t + i * 256];
        acc4.x += v.x; acc4.y += v.y; acc4.z += v.z; acc4.w += v.w;
    }

    __shared__ float4 shp[256];
    shp[t] = acc4;
    __syncthreads();
    if (t < 32) {
        float4 s = shp[t];
#pragma unroll
        for (int j = 1; j < 8; j++) {
            float4 v = shp[t + j * 32];
            s.x += v.x; s.y += v.y; s.z += v.z; s.w += v.w;
        }
        reinterpret_cast<float4*>(g_partial)[(size_t)(b * NSPLIT + split) * 32 + t] = s;
    }

    // ---- publish partials, count arrivals ----
    __threadfence();
    __syncthreads();
    __shared__ int is_last;
    if (t == 0) {
        unsigned old = atomicAdd(&g_bcnt[b], 1);
        is_last = (old == NSPLIT - 1);
        if (is_last) g_bcnt[b] = 0;          // self-reset: replay-safe
    }
    __syncthreads();
    if (!is_last) return;

    // ---- fused excite (runs in exactly one block per batch) ----
    __shared__ float s_mean[C];
    __shared__ float h[R];                   // 8 KB
    __shared__ float red[256];

    if (t < C) {
        const float* p = g_partial + (size_t)b * NSPLIT * C + t;
        float acc = 0.f;
#pragma unroll 14
        for (int k = 0; k < NSPLIT; k++) acc += __ldcg(&p[(size_t)k * C]);
        s_mean[t] = acc * (1.0f / (float)HW);
    }
    __syncthreads();

    // GEMM1 + tanh-approx GELU: 8 r's per thread (r = t + k*256, coalesced)
#pragma unroll
    for (int k = 0; k < 8; k++) {
        const int r = t + k * 256;
        float acc = b1[r];
#pragma unroll 16
        for (int c = 0; c < C; c++) acc += s_mean[c] * w1[(size_t)c * R + r];
        float u = acc;
        float inner = 0.7978845608028654f * (u + 0.044715f * u * u * u);
        h[r] = 0.5f * u * (1.0f + tanhf(inner));
    }
    __syncthreads();

    // GEMM2 split-K: c = t%128, slice = t/128 (1024 r each), then combine
    {
        const int c = t & (C - 1);
        const int slice = t >> 7;
        const int r0 = slice * (R / 2);
        const float* w2s = w2 + (size_t)r0 * C + c;
        float acc = 0.f;
#pragma unroll 8
        for (int rr = 0; rr < R / 2; rr++) acc += h[r0 + rr] * w2s[(size_t)rr * C];
        red[t] = acc;
    }
    __syncthreads();
    if (t < C) {
        float a = red[t] + red[t + 128] + b2[t];
        g_gate[b * C + t] = 1.0f / (1.0f + __expf(-a));
    }
}

// ---------------------------------------------------------------------------
// Kernel 2: scale for one group.  grid (NSPLIT, GBATCH), 256 threads.
// The group's x slice (102.8 MB) was just streamed through L2 by the pool
// kernel, so reads should mostly hit L2.  Traverse reversed (freshest first).
// ---------------------------------------------------------------------------
__global__ __launch_bounds__(256, 8)
void se_scale_kernel(const float* __restrict__ x, int g, float* __restrict__ out) {
    const int b   = g * GBATCH + (GBATCH - 1) - blockIdx.y;   // reversed batch
    const int blk = (NSPLIT - 1) - blockIdx.x;                // reversed split
    const int t = threadIdx.x;

    const int c4 = (t * 4) & (C - 1);        // fixed channel group per thread
    const float4 g4 = *reinterpret_cast<const float4*>(g_gate + b * C + c4);

    const size_t base = (size_t)b * F4_PER_B + (size_t)blk * F4_PER_BLK;
    const float4* __restrict__ xi = reinterpret_cast<const float4*>(x) + base;
    float4* __restrict__ xo = reinterpret_cast<float4*>(out) + base;

#pragma unroll
    for (int i = 0; i < 16; i++) {
        float4 v = __ldcs(&xi[t + i * 256]); // dead after use: evict-first
        v.x *= g4.x; v.y *= g4.y; v.z *= g4.z; v.w *= g4.w;
        __stcs(&xo[t + i * 256], v);         // streaming store
    }
}

extern "C" void kernel_launch(void* const* d_in, const int* in_sizes, int n_in,
                              void* d_out, int out_size) {
    const float* x  = (const float*)d_in[0];
    const float* w1 = (const float*)d_in[1];
    const float* b1 = (const float*)d_in[2];
    const float* w2 = (const float*)d_in[3];
    const float* b2 = (const float*)d_in[4];
    float* out = (float*)d_out;

    for (int g = 0; g < NGROUPS; g++) {
        se_pool_excite_kernel<<<dim3(NSPLIT, GBATCH), 256>>>(x, w1, b1, w2, b2, g);
        se_scale_kernel<<<dim3(NSPLIT, GBATCH), 256>>>(x, g, out);
    }
}

// round 13
// speedup vs baseline: 2.5756x; 2.5756x over previous
#include <cuda_runtime.h>
#include <math.h>

// Shapes
// x:  [32, 112, 112, 128] fp32  -> B=32, HW=12544, C=128
// w1: [128, 2048], b1: [2048], w2: [2048, 128], b2: [128]
#define B      32
#define HW     12544
#define C      128
#define R      2048
#define NSPLIT 98
#define NTOTAL (B * NSPLIT)
#define F4_PER_B  (HW * C / 4)               // 401408 float4 per batch
#define F4_PER_BLK (128 * C / 4)             // 4096 float4 per split
#define ECHUNKS 8                            // excite chunks per batch (256 r each)

// Scratch (device globals: allocation-free; counters self-reset -> replay-safe)
__device__ __align__(16) float g_partial[NTOTAL * C];   // 1.6 MB pool partials
__device__ __align__(16) float g_gp[B * ECHUNKS * C];   // gate partials, 128 KB
__device__ unsigned g_bcnt[B];                          // pool arrivals per batch
__device__ unsigned g_ecnt[B];                          // excite completions per batch

// ---------------------------------------------------------------------------
// Kernel 1: pool + overlapped distributed excite.  grid (NSPLIT+ECHUNKS, B),
// 256 threads.
//   blockIdx.x <  NSPLIT : pool block — partial sum of 128 rows, then bump
//                          this batch's arrival counter.
//   blockIdx.x >= NSPLIT : excite block — spin until the batch's 98 pool
//                          blocks arrived, then compute a 256-r chunk of
//                          GEMM1+tanh-GELU and its GEMM2 partial into g_gp.
// Excite blocks for early batches overlap later batches' pooling.
// Deadlock-free: 256 spinner blocks << resident capacity (6/SM * 148 SMs).
// ---------------------------------------------------------------------------
__global__ __launch_bounds__(256, 6)
void se_pool_excite_kernel(const float* __restrict__ x,
                           const float* __restrict__ w1, const float* __restrict__ b1,
                           const float* __restrict__ w2) {
    const int b = blockIdx.y;
    const int t = threadIdx.x;

    if (blockIdx.x < NSPLIT) {
        // ------------------ pool path ------------------
        const int split = blockIdx.x;
        const float4* __restrict__ xb =
            reinterpret_cast<const float4*>(x) + (size_t)b * F4_PER_B + (size_t)split * F4_PER_BLK;

        float4 acc = make_float4(0.f, 0.f, 0.f, 0.f);
#pragma unroll
        for (int i = 0; i < 16; i++) {       // 16 * 256 = 4096 float4
            float4 v = xb[t + i * 256];
            acc.x += v.x; acc.y += v.y; acc.z += v.z; acc.w += v.w;
        }

        __shared__ float4 sh[256];
        sh[t] = acc;
        __syncthreads();
        if (t < 32) {
            float4 s = sh[t];
#pragma unroll
            for (int j = 1; j < 8; j++) {
                float4 v = sh[t + j * 32];
                s.x += v.x; s.y += v.y; s.z += v.z; s.w += v.w;
            }
            reinterpret_cast<float4*>(g_partial)[(size_t)(b * NSPLIT + split) * 32 + t] = s;
        }
        // publish, then signal arrival
        __threadfence();
        __syncthreads();
        if (t == 0) atomicAdd(&g_bcnt[b], 1u);
        return;
    }

    // ------------------ excite path (spins until batch pooled) ------------------
    const int e = blockIdx.x - NSPLIT;       // 0..7, chunk of 256 r's

    if (t == 0) {
        while (*(volatile unsigned*)&g_bcnt[b] < NSPLIT) { __nanosleep(128); }
    }
    __syncthreads();
    __threadfence();                          // acquire partials

    __shared__ float s_mean[C];
    __shared__ float h_sh[256];
    __shared__ float red[256];

    // a) reduce pool partials -> mean s[128]
    if (t < C) {
        const float* p = g_partial + (size_t)b * NSPLIT * C + t;
        float acc = 0.f;
#pragma unroll 14
        for (int k = 0; k < NSPLIT; k++) acc += __ldcg(&p[(size_t)k * C]);
        s_mean[t] = acc * (1.0f / (float)HW);
    }
    __syncthreads();

    // b) GEMM1 + tanh-approx GELU: one r per thread (coalesced w1 columns)
    {
        const int r = e * 256 + t;
        float acc = b1[r];
#pragma unroll 16
        for (int c = 0; c < C; c++) acc += s_mean[c] * w1[(size_t)c * R + r];
        float u = acc;
        float inner = 0.7978845608028654f * (u + 0.044715f * u * u * u);
        h_sh[t] = 0.5f * u * (1.0f + tanhf(inner));
    }
    __syncthreads();

    // c) GEMM2 partial over this 256-r chunk: c = t%128, half = t/128
    {
        const int c = t & (C - 1);
        const int half = t >> 7;
        const int rbase = e * 256 + half * 128;
        const float* w2s = w2 + (size_t)rbase * C + c;
        float acc = 0.f;
#pragma unroll 16
        for (int rr = 0; rr < 128; rr++)
            acc += h_sh[half * 128 + rr] * w2s[(size_t)rr * C];
        red[t] = acc;
    }
    __syncthreads();
    if (t < C)
        g_gp[((size_t)b * ECHUNKS + e) * C + t] = red[t] + red[t + 128];

    // completion accounting; 8th excite block resets both counters (replay-safe)
    __threadfence();
    __syncthreads();
    if (t == 0) {
        unsigned old = atomicAdd(&g_ecnt[b], 1u);
        if (old == ECHUNKS - 1) { g_bcnt[b] = 0; g_ecnt[b] = 0; __threadfence(); }
    }
}

// ---------------------------------------------------------------------------
// Kernel 2: scale with fused gate finalize.  grid (NTOTAL), 256 threads.
// Reversed traversal (hits pool's L2-resident tail), __ldcs/__stcs streaming.
// ---------------------------------------------------------------------------
__global__ __launch_bounds__(256, 8)
void se_scale_kernel(const float* __restrict__ x, const float* __restrict__ b2,
                     float* __restrict__ out) {
    const int rid = (NTOTAL - 1) - blockIdx.x;   // reversed traversal
    const int b   = rid / NSPLIT;
    const int blk = rid % NSPLIT;
    const int t = threadIdx.x;

    // gate for this thread's fixed 4-channel group (g_gp/b2 L2-hot)
    const int c4 = (t * 4) & (C - 1);
    float4 g4;
    {
        float4 a = *reinterpret_cast<const float4*>(b2 + c4);
#pragma unroll
        for (int j = 0; j < ECHUNKS; j++) {
            float4 p = *reinterpret_cast<const float4*>(g_gp + ((size_t)b * ECHUNKS + j) * C + c4);
            a.x += p.x; a.y += p.y; a.z += p.z; a.w += p.w;
        }
        g4.x = 1.0f / (1.0f + __expf(-a.x));
        g4.y = 1.0f / (1.0f + __expf(-a.y));
        g4.z = 1.0f / (1.0f + __expf(-a.z));
        g4.w = 1.0f / (1.0f + __expf(-a.w));
    }

    const size_t base = (size_t)b * F4_PER_B + (size_t)blk * F4_PER_BLK;
    const float4* __restrict__ xi = reinterpret_cast<const float4*>(x) + base;
    float4* __restrict__ xo = reinterpret_cast<float4*>(out) + base;

#pragma unroll
    for (int i = 0; i < 16; i++) {
        float4 v = __ldcs(&xi[t + i * 256]);   // dead after use: evict-first
        v.x *= g4.x; v.y *= g4.y; v.z *= g4.z; v.w *= g4.w;
        __stcs(&xo[t + i * 256], v);           // streaming store
    }
}

extern "C" void kernel_launch(void* const* d_in, const int* in_sizes, int n_in,
                              void* d_out, int out_size) {
    const float* x  = (const float*)d_in[0];
    const float* w1 = (const float*)d_in[1];
    const float* b1 = (const float*)d_in[2];
    const float* w2 = (const float*)d_in[3];
    const float* b2 = (const float*)d_in[4];
    float* out = (float*)d_out;

    se_pool_excite_kernel<<<dim3(NSPLIT + ECHUNKS, B), 256>>>(x, w1, b1, w2);
    se_scale_kernel<<<NTOTAL, 256>>>(x, b2, out);
}